// round 1
// baseline (speedup 1.0000x reference)
#include <cuda_runtime.h>
#include <math.h>

// Problem constants
#define B_  2
#define T_  2048
#define C_  1024
#define H_  16
#define D_  64
#define BT_ (B_*T_)          // 4096
#define C3_ (3*C_)           // 3072

// Scratch (device globals: allocation-guard safe)
__device__ float g_qkv[BT_ * C3_];   // (B*T, 3C)
__device__ float g_y[BT_ * C_];      // (B*T, C) attention output

// ----------------------------------------------------------------------------
// SGEMM: C[M,N] = A[M,K] @ B[K,N] + bias[N]   (row-major, 128x128 tile, BK=8)
// 256 threads, each computes 8x8 micro-tile.
// Requires M%128==0, N%128==0, K%8==0 (true for all uses here).
// ----------------------------------------------------------------------------
__global__ __launch_bounds__(256) void sgemm_bias_kernel(
    const float* __restrict__ A, const float* __restrict__ B,
    const float* __restrict__ bias, float* __restrict__ C,
    int M, int N, int K)
{
    __shared__ __align__(16) float As[8][128];
    __shared__ __align__(16) float Bs[8][128];

    const int tid = threadIdx.x;
    const int tx = tid & 15;        // 0..15  -> output cols tx*8..+7
    const int ty = tid >> 4;        // 0..15  -> output rows ty*8..+7
    const int brow = blockIdx.y * 128;
    const int bcol = blockIdx.x * 128;

    // A load mapping: 128 rows x 8 cols = 1024 floats = 256 threads x float4
    const int arow  = tid >> 1;           // 0..127
    const int acol4 = (tid & 1) * 4;      // 0 or 4
    // B load mapping: 8 rows x 128 cols
    const int brow8 = tid >> 5;           // 0..7
    const int bcol4 = (tid & 31) * 4;     // 0..124

    float acc[8][8];
    #pragma unroll
    for (int i = 0; i < 8; i++)
        #pragma unroll
        for (int j = 0; j < 8; j++) acc[i][j] = 0.f;

    for (int k0 = 0; k0 < K; k0 += 8) {
        float4 av = *(const float4*)&A[(size_t)(brow + arow) * K + k0 + acol4];
        As[acol4 + 0][arow] = av.x;
        As[acol4 + 1][arow] = av.y;
        As[acol4 + 2][arow] = av.z;
        As[acol4 + 3][arow] = av.w;

        float4 bv = *(const float4*)&B[(size_t)(k0 + brow8) * N + bcol + bcol4];
        *(float4*)&Bs[brow8][bcol4] = bv;

        __syncthreads();

        #pragma unroll
        for (int k = 0; k < 8; k++) {
            float a[8], b[8];
            *(float4*)&a[0] = *(const float4*)&As[k][ty * 8];
            *(float4*)&a[4] = *(const float4*)&As[k][ty * 8 + 4];
            *(float4*)&b[0] = *(const float4*)&Bs[k][tx * 8];
            *(float4*)&b[4] = *(const float4*)&Bs[k][tx * 8 + 4];
            #pragma unroll
            for (int i = 0; i < 8; i++)
                #pragma unroll
                for (int j = 0; j < 8; j++)
                    acc[i][j] += a[i] * b[j];
        }
        __syncthreads();
    }

    #pragma unroll
    for (int i = 0; i < 8; i++) {
        const size_t row = brow + ty * 8 + i;
        #pragma unroll
        for (int j = 0; j < 8; j += 4) {
            const int col = bcol + tx * 8 + j;
            float4 o;
            o.x = acc[i][j + 0] + bias[col + 0];
            o.y = acc[i][j + 1] + bias[col + 1];
            o.z = acc[i][j + 2] + bias[col + 2];
            o.w = acc[i][j + 3] + bias[col + 3];
            *(float4*)&C[row * N + col] = o;
        }
    }
}

// ----------------------------------------------------------------------------
// Flash attention (causal), fp32.
// Grid: (T/64, H, B). Block: 256 threads (16x16).
// Q tile = 64 rows, K tile = 32 keys, D = 64.
// Reads q,k,v slices from g_qkv; writes g_y[(b*T+t)*C + h*64 + d].
// ----------------------------------------------------------------------------
__global__ __launch_bounds__(256) void attn_kernel(const float* __restrict__ amask)
{
    __shared__ __align__(16) float Qs[64 * 65];   // [row][d] pad 65
    __shared__ __align__(16) float Ks[32 * 65];   // [key][d] pad 65
    __shared__ __align__(16) float Vs[32 * 65];   // [key][d] pad 65
    __shared__ __align__(16) float Ps[64 * 33];   // [row][key] pad 33

    const int qt = blockIdx.x;
    const int h  = blockIdx.y;
    const int b  = blockIdx.z;
    const int tid = threadIdx.x;
    const int tx = tid & 15;   // key-cols tx*2 (S) / d-cols tx*4 (O)
    const int ty = tid >> 4;   // q-rows ty*4
    const int qbase = qt * 64;

    // Load Q tile: 64x64 floats
    for (int idx = tid; idx < 64 * 16; idx += 256) {
        const int r = idx >> 4;
        const int c4 = (idx & 15) * 4;
        float4 v = *(const float4*)&g_qkv[(size_t)(b * T_ + qbase + r) * C3_ + h * D_ + c4];
        Qs[r * 65 + c4 + 0] = v.x;
        Qs[r * 65 + c4 + 1] = v.y;
        Qs[r * 65 + c4 + 2] = v.z;
        Qs[r * 65 + c4 + 3] = v.w;
    }

    float m_i[4], l_i[4], o[4][4];
    #pragma unroll
    for (int i = 0; i < 4; i++) {
        m_i[i] = -INFINITY;
        l_i[i] = 0.f;
        #pragma unroll
        for (int j = 0; j < 4; j++) o[i][j] = 0.f;
    }

    const int nkt = 2 * (qt + 1);   // causal: keys up to qbase+63, tiles of 32
    for (int kt = 0; kt < nkt; kt++) {
        const int kbase = kt * 32;
        __syncthreads();   // protect Ks/Vs (prev PV) and Qs (first iter load)

        // Load K,V tiles: 32x64 each
        for (int idx = tid; idx < 32 * 16; idx += 256) {
            const int r = idx >> 4;
            const int c4 = (idx & 15) * 4;
            const size_t rowoff = (size_t)(b * T_ + kbase + r) * C3_ + h * D_ + c4;
            float4 kv = *(const float4*)&g_qkv[rowoff + C_];
            Ks[r * 65 + c4 + 0] = kv.x;
            Ks[r * 65 + c4 + 1] = kv.y;
            Ks[r * 65 + c4 + 2] = kv.z;
            Ks[r * 65 + c4 + 3] = kv.w;
            float4 vv = *(const float4*)&g_qkv[rowoff + 2 * C_];
            Vs[r * 65 + c4 + 0] = vv.x;
            Vs[r * 65 + c4 + 1] = vv.y;
            Vs[r * 65 + c4 + 2] = vv.z;
            Vs[r * 65 + c4 + 3] = vv.w;
        }
        __syncthreads();

        // S = Q K^T for this tile: s[4 rows][2 key-cols]
        float s[4][2];
        #pragma unroll
        for (int i = 0; i < 4; i++) { s[i][0] = 0.f; s[i][1] = 0.f; }
        for (int d = 0; d < 64; d++) {
            float q[4], k[2];
            #pragma unroll
            for (int i = 0; i < 4; i++) q[i] = Qs[(ty * 4 + i) * 65 + d];
            #pragma unroll
            for (int j = 0; j < 2; j++) k[j] = Ks[(tx * 2 + j) * 65 + d];
            #pragma unroll
            for (int i = 0; i < 4; i++)
                #pragma unroll
                for (int j = 0; j < 2; j++)
                    s[i][j] += q[i] * k[j];
        }

        // scale + additive padding mask + causal mask
        float am[2];
        #pragma unroll
        for (int j = 0; j < 2; j++)
            am[j] = amask[b * T_ + kbase + tx * 2 + j];
        #pragma unroll
        for (int i = 0; i < 4; i++) {
            const int qg = qbase + ty * 4 + i;
            #pragma unroll
            for (int j = 0; j < 2; j++) {
                const int kg = kbase + tx * 2 + j;
                s[i][j] = (kg <= qg) ? (s[i][j] * 0.125f + am[j]) : -INFINITY;
            }
        }

        // online softmax per row (reduce across 16 tx lanes, width 16)
        #pragma unroll
        for (int i = 0; i < 4; i++) {
            float mx = fmaxf(s[i][0], s[i][1]);
            #pragma unroll
            for (int off = 8; off > 0; off >>= 1)
                mx = fmaxf(mx, __shfl_xor_sync(0xffffffffu, mx, off, 16));
            const float m_new = fmaxf(m_i[i], mx);
            const float p0 = expf(s[i][0] - m_new);
            const float p1 = expf(s[i][1] - m_new);
            float sum = p0 + p1;
            #pragma unroll
            for (int off = 8; off > 0; off >>= 1)
                sum += __shfl_xor_sync(0xffffffffu, sum, off, 16);
            const float corr = expf(m_i[i] - m_new);
            l_i[i] = l_i[i] * corr + sum;
            m_i[i] = m_new;
            #pragma unroll
            for (int j = 0; j < 4; j++) o[i][j] *= corr;
            Ps[(ty * 4 + i) * 33 + tx * 2 + 0] = p0;
            Ps[(ty * 4 + i) * 33 + tx * 2 + 1] = p1;
        }
        __syncthreads();

        // O += P @ V : o[4 rows][4 d-cols]
        #pragma unroll 4
        for (int k = 0; k < 32; k++) {
            float p[4], v[4];
            #pragma unroll
            for (int i = 0; i < 4; i++) p[i] = Ps[(ty * 4 + i) * 33 + k];
            #pragma unroll
            for (int j = 0; j < 4; j++) v[j] = Vs[k * 65 + tx * 4 + j];
            #pragma unroll
            for (int i = 0; i < 4; i++)
                #pragma unroll
                for (int j = 0; j < 4; j++)
                    o[i][j] += p[i] * v[j];
        }
    }

    // finalize and write y
    #pragma unroll
    for (int i = 0; i < 4; i++) {
        const float inv = 1.f / l_i[i];
        const size_t row = (size_t)(b * T_ + qbase + ty * 4 + i);
        #pragma unroll
        for (int j = 0; j < 4; j++)
            g_y[row * C_ + h * D_ + tx * 4 + j] = o[i][j] * inv;
    }
}

// ----------------------------------------------------------------------------
// Launch
// Inputs (metadata order): 0 x, 1 attention_mask, 2 attention_bias,
//                          3 W_attn, 4 b_attn, 5 W_proj, 6 b_proj
// ----------------------------------------------------------------------------
extern "C" void kernel_launch(void* const* d_in, const int* in_sizes, int n_in,
                              void* d_out, int out_size)
{
    (void)in_sizes; (void)n_in; (void)out_size;
    const float* x      = (const float*)d_in[0];
    const float* amask  = (const float*)d_in[1];
    // d_in[2] attention_bias: lower-triangular causal structure, applied analytically
    const float* W_attn = (const float*)d_in[3];
    const float* b_attn = (const float*)d_in[4];
    const float* W_proj = (const float*)d_in[5];
    const float* b_proj = (const float*)d_in[6];
    float* out = (float*)d_out;

    float* qkv_ptr = nullptr;
    float* y_ptr = nullptr;
    cudaGetSymbolAddress((void**)&qkv_ptr, g_qkv);
    cudaGetSymbolAddress((void**)&y_ptr, g_y);

    // 1) QKV projection: (4096,1024) @ (1024,3072) + b_attn
    dim3 g1(C3_ / 128, BT_ / 128);
    sgemm_bias_kernel<<<g1, 256>>>(x, W_attn, b_attn, qkv_ptr, BT_, C3_, C_);

    // 2) Causal flash attention
    dim3 g2(T_ / 64, H_, B_);
    attn_kernel<<<g2, 256>>>(amask);

    // 3) Output projection: (4096,1024) @ (1024,1024) + b_proj
    dim3 g3(C_ / 128, BT_ / 128);
    sgemm_bias_kernel<<<g3, 256>>>(y_ptr, W_proj, b_proj, out, BT_, C_, C_);
}

// round 3
// speedup vs baseline: 1.4048x; 1.4048x over previous
#include <cuda_runtime.h>
#include <cstdint>
#include <math.h>

// Problem constants
#define B_  2
#define T_  2048
#define C_  1024
#define H_  16
#define D_  64
#define BT_ (B_*T_)          // 4096
#define C3_ (3*C_)           // 3072

// Scratch (device globals: allocation-guard safe)
__device__ float g_qkv[BT_ * C3_];   // (B*T, 3C)
__device__ float g_y[BT_ * C_];      // (B*T, C) attention output
__device__ float g_WT1[C3_ * C_];    // W_attn^T  (3072 x 1024), tf32-rounded
__device__ float g_WT2[C_ * C_];     // W_proj^T  (1024 x 1024), tf32-rounded

__device__ __forceinline__ float to_tf32(float f) {
    uint32_t u;
    asm("cvt.rna.tf32.f32 %0, %1;" : "=r"(u) : "f"(f));
    return __uint_as_float(u);
}

__device__ __forceinline__ void mma_tf32(float* d, const uint32_t* a, const uint32_t* b) {
    asm volatile(
        "mma.sync.aligned.m16n8k8.row.col.f32.tf32.tf32.f32 "
        "{%0,%1,%2,%3}, {%4,%5,%6,%7}, {%8,%9}, {%0,%1,%2,%3};"
        : "+f"(d[0]), "+f"(d[1]), "+f"(d[2]), "+f"(d[3])
        : "r"(a[0]), "r"(a[1]), "r"(a[2]), "r"(a[3]), "r"(b[0]), "r"(b[1]));
}

// ============================================================================
// Transpose + tf32-round: out[n][k] = tf32(in[k][n]).  in: R x Cc, out: Cc x R.
// block (32,8), grid (Cc/32, R/32)
// ============================================================================
__global__ void transpose_tf32_kernel(const float* __restrict__ in, float* __restrict__ out,
                                      int R, int Cc)
{
    __shared__ float tile[32][33];
    const int bx = blockIdx.x * 32;
    const int by = blockIdx.y * 32;
    #pragma unroll
    for (int j = 0; j < 32; j += 8)
        tile[threadIdx.y + j][threadIdx.x] = in[(size_t)(by + threadIdx.y + j) * Cc + bx + threadIdx.x];
    __syncthreads();
    #pragma unroll
    for (int j = 0; j < 32; j += 8)
        out[(size_t)(bx + threadIdx.y + j) * R + by + threadIdx.x] =
            to_tf32(tile[threadIdx.x][threadIdx.y + j]);
}

// ============================================================================
// tf32 mma.sync GEMM:  Cmat[M,N] = A[M,K] @ BT[N,K]^T + bias[N]
// A row-major fp32 (tf32-rounded on smem store); BT row-major, already tf32.
// Block 128x128, BK=16, 256 threads (8 warps, 64x32 warp tiles), double buffer.
// Smem layout [kq][m][4]: all accesses bank-conflict-free.
// ============================================================================
__global__ __launch_bounds__(256, 2) void gemm_mma_kernel(
    const float* __restrict__ A, const float* __restrict__ BT,
    const float* __restrict__ bias, float* __restrict__ Cmat,
    int M, int N, int K)
{
    __shared__ float As[2][4][128][4];   // [buf][kq][m][ic]
    __shared__ float Bs[2][4][128][4];   // [buf][kq][n][ic]

    const int tid  = threadIdx.x;
    const int lane = tid & 31;
    const int warp = tid >> 5;
    const int wr = warp >> 2;            // 0..1 -> m offset wr*64
    const int wc = warp & 3;             // 0..3 -> n offset wc*32
    const int g  = lane >> 2;            // 0..7
    const int kc = lane & 3;             // 0..3

    const int m0 = blockIdx.y * 128;
    const int n0 = blockIdx.x * 128;

    // global loader mapping: thread -> (row lm, k-quad lkq); 2 rows per thread
    const int lm  = tid >> 2;            // 0..63
    const int lkq = tid & 3;             // 0..3

    float acc[4][4][4];
    #pragma unroll
    for (int mf = 0; mf < 4; mf++)
        #pragma unroll
        for (int nf = 0; nf < 4; nf++)
            #pragma unroll
            for (int r = 0; r < 4; r++) acc[mf][nf][r] = 0.f;

    const int nch = K >> 4;              // K/16

    // ---- prologue: chunk 0 -> buffer 0
    {
        #pragma unroll
        for (int it = 0; it < 2; it++) {
            const int m = lm + it * 64;
            float4 va = *(const float4*)&A[(size_t)(m0 + m) * K + 4 * lkq];
            va.x = to_tf32(va.x); va.y = to_tf32(va.y);
            va.z = to_tf32(va.z); va.w = to_tf32(va.w);
            *(float4*)&As[0][lkq][m][0] = va;
            float4 vb = *(const float4*)&BT[(size_t)(n0 + m) * K + 4 * lkq];
            *(float4*)&Bs[0][lkq][m][0] = vb;
        }
    }
    __syncthreads();

    for (int icn = 0; icn < nch; icn++) {
        const int cur = icn & 1;

        float4 pa[2], pb[2];
        const bool more = (icn + 1) < nch;
        if (more) {
            const int k0 = (icn + 1) << 4;
            #pragma unroll
            for (int it = 0; it < 2; it++) {
                const int m = lm + it * 64;
                pa[it] = *(const float4*)&A[(size_t)(m0 + m) * K + k0 + 4 * lkq];
                pb[it] = *(const float4*)&BT[(size_t)(n0 + m) * K + k0 + 4 * lkq];
            }
        }

        // compute on buffer cur
        #pragma unroll
        for (int t = 0; t < 2; t++) {
            uint32_t bf[4][2];
            #pragma unroll
            for (int nf = 0; nf < 4; nf++) {
                const int n = wc * 32 + nf * 8 + g;
                bf[nf][0] = __float_as_uint(Bs[cur][2 * t + 0][n][kc]);
                bf[nf][1] = __float_as_uint(Bs[cur][2 * t + 1][n][kc]);
            }
            #pragma unroll
            for (int mf = 0; mf < 4; mf++) {
                const int m = wr * 64 + mf * 16 + g;
                uint32_t af[4];
                af[0] = __float_as_uint(As[cur][2 * t + 0][m][kc]);
                af[1] = __float_as_uint(As[cur][2 * t + 0][m + 8][kc]);
                af[2] = __float_as_uint(As[cur][2 * t + 1][m][kc]);
                af[3] = __float_as_uint(As[cur][2 * t + 1][m + 8][kc]);
                #pragma unroll
                for (int nf = 0; nf < 4; nf++)
                    mma_tf32(acc[mf][nf], af, bf[nf]);
            }
        }

        if (more) {
            const int nxt = cur ^ 1;
            #pragma unroll
            for (int it = 0; it < 2; it++) {
                const int m = lm + it * 64;
                float4 va = pa[it];
                va.x = to_tf32(va.x); va.y = to_tf32(va.y);
                va.z = to_tf32(va.z); va.w = to_tf32(va.w);
                *(float4*)&As[nxt][lkq][m][0] = va;
                *(float4*)&Bs[nxt][lkq][m][0] = pb[it];
            }
            __syncthreads();
        }
    }

    // ---- epilogue: acc -> gmem with bias
    #pragma unroll
    for (int mf = 0; mf < 4; mf++) {
        const int row = m0 + wr * 64 + mf * 16 + g;
        #pragma unroll
        for (int nf = 0; nf < 4; nf++) {
            const int col = n0 + wc * 32 + nf * 8 + kc * 2;
            const float b0 = bias[col];
            const float b1 = bias[col + 1];
            float2 o0 = { acc[mf][nf][0] + b0, acc[mf][nf][1] + b1 };
            float2 o1 = { acc[mf][nf][2] + b0, acc[mf][nf][3] + b1 };
            *(float2*)&Cmat[(size_t)row * N + col] = o0;
            *(float2*)&Cmat[(size_t)(row + 8) * N + col] = o1;
        }
    }
}

// ----------------------------------------------------------------------------
// Flash attention (causal), fp32. Grid: (T/64, H, B). Block: 256 (16x16).
// ----------------------------------------------------------------------------
__global__ __launch_bounds__(256) void attn_kernel(const float* __restrict__ amask)
{
    __shared__ __align__(16) float Qs[64 * 65];
    __shared__ __align__(16) float Ks[32 * 65];
    __shared__ __align__(16) float Vs[32 * 65];
    __shared__ __align__(16) float Ps[64 * 33];

    const int qt = blockIdx.x;
    const int h  = blockIdx.y;
    const int b  = blockIdx.z;
    const int tid = threadIdx.x;
    const int tx = tid & 15;
    const int ty = tid >> 4;
    const int qbase = qt * 64;

    for (int idx = tid; idx < 64 * 16; idx += 256) {
        const int r = idx >> 4;
        const int c4 = (idx & 15) * 4;
        float4 v = *(const float4*)&g_qkv[(size_t)(b * T_ + qbase + r) * C3_ + h * D_ + c4];
        Qs[r * 65 + c4 + 0] = v.x;
        Qs[r * 65 + c4 + 1] = v.y;
        Qs[r * 65 + c4 + 2] = v.z;
        Qs[r * 65 + c4 + 3] = v.w;
    }

    float m_i[4], l_i[4], o[4][4];
    #pragma unroll
    for (int i = 0; i < 4; i++) {
        m_i[i] = -INFINITY;
        l_i[i] = 0.f;
        #pragma unroll
        for (int j = 0; j < 4; j++) o[i][j] = 0.f;
    }

    const int nkt = 2 * (qt + 1);
    for (int kt = 0; kt < nkt; kt++) {
        const int kbase = kt * 32;
        __syncthreads();

        for (int idx = tid; idx < 32 * 16; idx += 256) {
            const int r = idx >> 4;
            const int c4 = (idx & 15) * 4;
            const size_t rowoff = (size_t)(b * T_ + kbase + r) * C3_ + h * D_ + c4;
            float4 kv = *(const float4*)&g_qkv[rowoff + C_];
            Ks[r * 65 + c4 + 0] = kv.x;
            Ks[r * 65 + c4 + 1] = kv.y;
            Ks[r * 65 + c4 + 2] = kv.z;
            Ks[r * 65 + c4 + 3] = kv.w;
            float4 vv = *(const float4*)&g_qkv[rowoff + 2 * C_];
            Vs[r * 65 + c4 + 0] = vv.x;
            Vs[r * 65 + c4 + 1] = vv.y;
            Vs[r * 65 + c4 + 2] = vv.z;
            Vs[r * 65 + c4 + 3] = vv.w;
        }
        __syncthreads();

        float s[4][2];
        #pragma unroll
        for (int i = 0; i < 4; i++) { s[i][0] = 0.f; s[i][1] = 0.f; }
        for (int d = 0; d < 64; d++) {
            float q[4], k[2];
            #pragma unroll
            for (int i = 0; i < 4; i++) q[i] = Qs[(ty * 4 + i) * 65 + d];
            #pragma unroll
            for (int j = 0; j < 2; j++) k[j] = Ks[(tx * 2 + j) * 65 + d];
            #pragma unroll
            for (int i = 0; i < 4; i++)
                #pragma unroll
                for (int j = 0; j < 2; j++)
                    s[i][j] += q[i] * k[j];
        }

        float am[2];
        #pragma unroll
        for (int j = 0; j < 2; j++)
            am[j] = amask[b * T_ + kbase + tx * 2 + j];
        #pragma unroll
        for (int i = 0; i < 4; i++) {
            const int qg = qbase + ty * 4 + i;
            #pragma unroll
            for (int j = 0; j < 2; j++) {
                const int kg = kbase + tx * 2 + j;
                s[i][j] = (kg <= qg) ? (s[i][j] * 0.125f + am[j]) : -INFINITY;
            }
        }

        #pragma unroll
        for (int i = 0; i < 4; i++) {
            float mx = fmaxf(s[i][0], s[i][1]);
            #pragma unroll
            for (int off = 8; off > 0; off >>= 1)
                mx = fmaxf(mx, __shfl_xor_sync(0xffffffffu, mx, off, 16));
            const float m_new = fmaxf(m_i[i], mx);
            const float p0 = expf(s[i][0] - m_new);
            const float p1 = expf(s[i][1] - m_new);
            float sum = p0 + p1;
            #pragma unroll
            for (int off = 8; off > 0; off >>= 1)
                sum += __shfl_xor_sync(0xffffffffu, sum, off, 16);
            const float corr = expf(m_i[i] - m_new);
            l_i[i] = l_i[i] * corr + sum;
            m_i[i] = m_new;
            #pragma unroll
            for (int j = 0; j < 4; j++) o[i][j] *= corr;
            Ps[(ty * 4 + i) * 33 + tx * 2 + 0] = p0;
            Ps[(ty * 4 + i) * 33 + tx * 2 + 1] = p1;
        }
        __syncthreads();

        #pragma unroll 4
        for (int k = 0; k < 32; k++) {
            float p[4], v[4];
            #pragma unroll
            for (int i = 0; i < 4; i++) p[i] = Ps[(ty * 4 + i) * 33 + k];
            #pragma unroll
            for (int j = 0; j < 4; j++) v[j] = Vs[k * 65 + tx * 4 + j];
            #pragma unroll
            for (int i = 0; i < 4; i++)
                #pragma unroll
                for (int j = 0; j < 4; j++)
                    o[i][j] += p[i] * v[j];
        }
    }

    #pragma unroll
    for (int i = 0; i < 4; i++) {
        const float inv = 1.f / l_i[i];
        const size_t row = (size_t)(b * T_ + qbase + ty * 4 + i);
        #pragma unroll
        for (int j = 0; j < 4; j++)
            g_y[row * C_ + h * D_ + tx * 4 + j] = o[i][j] * inv;
    }
}

// ----------------------------------------------------------------------------
// Launch.  Inputs: 0 x, 1 attention_mask, 2 attention_bias, 3 W_attn,
//                  4 b_attn, 5 W_proj, 6 b_proj
// ----------------------------------------------------------------------------
extern "C" void kernel_launch(void* const* d_in, const int* in_sizes, int n_in,
                              void* d_out, int out_size)
{
    (void)in_sizes; (void)n_in; (void)out_size;
    const float* x      = (const float*)d_in[0];
    const float* amask  = (const float*)d_in[1];
    const float* W_attn = (const float*)d_in[3];
    const float* b_attn = (const float*)d_in[4];
    const float* W_proj = (const float*)d_in[5];
    const float* b_proj = (const float*)d_in[6];
    float* out = (float*)d_out;

    float *qkv_ptr = nullptr, *y_ptr = nullptr, *wt1 = nullptr, *wt2 = nullptr;
    cudaGetSymbolAddress((void**)&qkv_ptr, g_qkv);
    cudaGetSymbolAddress((void**)&y_ptr, g_y);
    cudaGetSymbolAddress((void**)&wt1, g_WT1);
    cudaGetSymbolAddress((void**)&wt2, g_WT2);

    // 0) Pre-transpose + tf32-round the weights
    transpose_tf32_kernel<<<dim3(C3_ / 32, C_ / 32), dim3(32, 8)>>>(W_attn, wt1, C_, C3_);
    transpose_tf32_kernel<<<dim3(C_ / 32, C_ / 32), dim3(32, 8)>>>(W_proj, wt2, C_, C_);

    // 1) QKV projection: (4096,1024) @ (1024,3072) + b_attn  -> g_qkv
    gemm_mma_kernel<<<dim3(C3_ / 128, BT_ / 128), 256>>>(x, wt1, b_attn, qkv_ptr, BT_, C3_, C_);

    // 2) Causal flash attention -> g_y
    attn_kernel<<<dim3(T_ / 64, H_, B_), 256>>>(amask);

    // 3) Output projection: (4096,1024) @ (1024,1024) + b_proj -> out
    gemm_mma_kernel<<<dim3(C_ / 128, BT_ / 128), 256>>>(y_ptr, wt2, b_proj, out, BT_, C_, C_);
}

// round 4
// speedup vs baseline: 2.9264x; 2.0832x over previous
#include <cuda_runtime.h>
#include <cstdint>
#include <math.h>

// Problem constants
#define B_  2
#define T_  2048
#define C_  1024
#define H_  16
#define D_  64
#define BT_ (B_*T_)          // 4096
#define C3_ (3*C_)           // 3072

// Scratch (device globals: allocation-guard safe)
__device__ float g_qkv[BT_ * C3_];   // (B*T, 3C)
__device__ float g_y[BT_ * C_];      // (B*T, C) attention output
__device__ float g_WT1[C3_ * C_];    // W_attn^T  (3072 x 1024), tf32-rounded
__device__ float g_WT2[C_ * C_];     // W_proj^T  (1024 x 1024), tf32-rounded

__device__ __forceinline__ float to_tf32(float f) {
    uint32_t u;
    asm("cvt.rna.tf32.f32 %0, %1;" : "=r"(u) : "f"(f));
    return __uint_as_float(u);
}

__device__ __forceinline__ void mma_tf32(float* d, const uint32_t* a, const uint32_t* b) {
    asm volatile(
        "mma.sync.aligned.m16n8k8.row.col.f32.tf32.tf32.f32 "
        "{%0,%1,%2,%3}, {%4,%5,%6,%7}, {%8,%9}, {%0,%1,%2,%3};"
        : "+f"(d[0]), "+f"(d[1]), "+f"(d[2]), "+f"(d[3])
        : "r"(a[0]), "r"(a[1]), "r"(a[2]), "r"(a[3]), "r"(b[0]), "r"(b[1]));
}

// ============================================================================
// Transpose + tf32-round: out[n][k] = tf32(in[k][n]).
// ============================================================================
__global__ void transpose_tf32_kernel(const float* __restrict__ in, float* __restrict__ out,
                                      int R, int Cc)
{
    __shared__ float tile[32][33];
    const int bx = blockIdx.x * 32;
    const int by = blockIdx.y * 32;
    #pragma unroll
    for (int j = 0; j < 32; j += 8)
        tile[threadIdx.y + j][threadIdx.x] = in[(size_t)(by + threadIdx.y + j) * Cc + bx + threadIdx.x];
    __syncthreads();
    #pragma unroll
    for (int j = 0; j < 32; j += 8)
        out[(size_t)(bx + threadIdx.y + j) * R + by + threadIdx.x] =
            to_tf32(tile[threadIdx.x][threadIdx.y + j]);
}

// ============================================================================
// tf32 mma.sync GEMM:  Cmat[M,N] = A[M,K] @ BT[N,K]^T + bias[N]
// ============================================================================
__global__ __launch_bounds__(256, 2) void gemm_mma_kernel(
    const float* __restrict__ A, const float* __restrict__ BT,
    const float* __restrict__ bias, float* __restrict__ Cmat,
    int M, int N, int K)
{
    __shared__ float As[2][4][128][4];
    __shared__ float Bs[2][4][128][4];

    const int tid  = threadIdx.x;
    const int lane = tid & 31;
    const int warp = tid >> 5;
    const int wr = warp >> 2;
    const int wc = warp & 3;
    const int g  = lane >> 2;
    const int kc = lane & 3;

    const int m0 = blockIdx.y * 128;
    const int n0 = blockIdx.x * 128;

    const int lm  = tid >> 2;
    const int lkq = tid & 3;

    float acc[4][4][4];
    #pragma unroll
    for (int mf = 0; mf < 4; mf++)
        #pragma unroll
        for (int nf = 0; nf < 4; nf++)
            #pragma unroll
            for (int r = 0; r < 4; r++) acc[mf][nf][r] = 0.f;

    const int nch = K >> 4;

    {
        #pragma unroll
        for (int it = 0; it < 2; it++) {
            const int m = lm + it * 64;
            float4 va = *(const float4*)&A[(size_t)(m0 + m) * K + 4 * lkq];
            va.x = to_tf32(va.x); va.y = to_tf32(va.y);
            va.z = to_tf32(va.z); va.w = to_tf32(va.w);
            *(float4*)&As[0][lkq][m][0] = va;
            float4 vb = *(const float4*)&BT[(size_t)(n0 + m) * K + 4 * lkq];
            *(float4*)&Bs[0][lkq][m][0] = vb;
        }
    }
    __syncthreads();

    for (int icn = 0; icn < nch; icn++) {
        const int cur = icn & 1;

        float4 pa[2], pb[2];
        const bool more = (icn + 1) < nch;
        if (more) {
            const int k0 = (icn + 1) << 4;
            #pragma unroll
            for (int it = 0; it < 2; it++) {
                const int m = lm + it * 64;
                pa[it] = *(const float4*)&A[(size_t)(m0 + m) * K + k0 + 4 * lkq];
                pb[it] = *(const float4*)&BT[(size_t)(n0 + m) * K + k0 + 4 * lkq];
            }
        }

        #pragma unroll
        for (int t = 0; t < 2; t++) {
            uint32_t bf[4][2];
            #pragma unroll
            for (int nf = 0; nf < 4; nf++) {
                const int n = wc * 32 + nf * 8 + g;
                bf[nf][0] = __float_as_uint(Bs[cur][2 * t + 0][n][kc]);
                bf[nf][1] = __float_as_uint(Bs[cur][2 * t + 1][n][kc]);
            }
            #pragma unroll
            for (int mf = 0; mf < 4; mf++) {
                const int m = wr * 64 + mf * 16 + g;
                uint32_t af[4];
                af[0] = __float_as_uint(As[cur][2 * t + 0][m][kc]);
                af[1] = __float_as_uint(As[cur][2 * t + 0][m + 8][kc]);
                af[2] = __float_as_uint(As[cur][2 * t + 1][m][kc]);
                af[3] = __float_as_uint(As[cur][2 * t + 1][m + 8][kc]);
                #pragma unroll
                for (int nf = 0; nf < 4; nf++)
                    mma_tf32(acc[mf][nf], af, bf[nf]);
            }
        }

        if (more) {
            const int nxt = cur ^ 1;
            #pragma unroll
            for (int it = 0; it < 2; it++) {
                const int m = lm + it * 64;
                float4 va = pa[it];
                va.x = to_tf32(va.x); va.y = to_tf32(va.y);
                va.z = to_tf32(va.z); va.w = to_tf32(va.w);
                *(float4*)&As[nxt][lkq][m][0] = va;
                *(float4*)&Bs[nxt][lkq][m][0] = pb[it];
            }
            __syncthreads();
        }
    }

    #pragma unroll
    for (int mf = 0; mf < 4; mf++) {
        const int row = m0 + wr * 64 + mf * 16 + g;
        #pragma unroll
        for (int nf = 0; nf < 4; nf++) {
            const int col = n0 + wc * 32 + nf * 8 + kc * 2;
            const float b0 = bias[col];
            const float b1 = bias[col + 1];
            float2 o0 = { acc[mf][nf][0] + b0, acc[mf][nf][1] + b1 };
            float2 o1 = { acc[mf][nf][2] + b0, acc[mf][nf][3] + b1 };
            *(float2*)&Cmat[(size_t)row * N + col] = o0;
            *(float2*)&Cmat[(size_t)(row + 8) * N + col] = o1;
        }
    }
}

// ============================================================================
// Flash attention (causal) with tf32 mma.sync.
// Grid (T/64, H, B). Block 128 (4 warps). Q tile 64 (16 rows/warp), K tile 32.
// Smem strides: Q/K 68, V 72, P 36 -> conflict-free fragment access.
// ============================================================================
#define QS_STRIDE 68
#define KS_STRIDE 68
#define VS_STRIDE 72
#define PS_STRIDE 36

__global__ __launch_bounds__(128) void attn_mma_kernel(const float* __restrict__ amask)
{
    __shared__ __align__(16) float Qs[64 * QS_STRIDE];   // reused as P after Q frag cache
    __shared__ __align__(16) float Ks[32 * KS_STRIDE];
    __shared__ __align__(16) float Vs[32 * VS_STRIDE];
    __shared__ float Ams[32];

    const int qt = blockIdx.x;
    const int hh = blockIdx.y;
    const int bb = blockIdx.z;
    const int tid = threadIdx.x;
    const int lane = tid & 31;
    const int w = tid >> 5;
    const int r = lane >> 2;      // quad row 0..7
    const int c = lane & 3;       // quad col 0..3
    const int qbase = qt * 64;
    const int qlo = qbase + w * 16;   // warp's first q row

    // --- load Q tile (tf32-rounded) ---
    for (int i = tid; i < 64 * 16; i += 128) {
        const int row = i >> 4;
        const int c4 = (i & 15) * 4;
        float4 v = *(const float4*)&g_qkv[(size_t)(bb * T_ + qbase + row) * C3_ + hh * D_ + c4];
        v.x = to_tf32(v.x); v.y = to_tf32(v.y);
        v.z = to_tf32(v.z); v.w = to_tf32(v.w);
        *(float4*)&Qs[row * QS_STRIDE + c4] = v;
    }
    __syncthreads();

    // --- cache Q fragments in registers: qa[kf][4] for m16k64 ---
    uint32_t qa[8][4];
    #pragma unroll
    for (int kf = 0; kf < 8; kf++) {
        const int row = w * 16 + r;
        const int col = kf * 8 + c;
        qa[kf][0] = __float_as_uint(Qs[row * QS_STRIDE + col]);
        qa[kf][1] = __float_as_uint(Qs[(row + 8) * QS_STRIDE + col]);
        qa[kf][2] = __float_as_uint(Qs[row * QS_STRIDE + col + 4]);
        qa[kf][3] = __float_as_uint(Qs[(row + 8) * QS_STRIDE + col + 4]);
    }
    __syncthreads();

    float* Ps = Qs;   // P stage reuses Q smem (Q now register-resident)

    float o[8][4];
    #pragma unroll
    for (int nb = 0; nb < 8; nb++)
        #pragma unroll
        for (int j = 0; j < 4; j++) o[nb][j] = 0.f;
    float mrow[2] = { -INFINITY, -INFINITY };
    float lrow[2] = { 0.f, 0.f };

    const int nkt = 2 * qt + 2;
    for (int kt = 0; kt < nkt; kt++) {
        const int kbase = kt * 32;
        if (kt) __syncthreads();   // all warps done with Ks/Vs/Ps of prev tile

        // --- load K,V tiles (tf32) + mask slice ---
        for (int i = tid; i < 32 * 16; i += 128) {
            const int row = i >> 4;
            const int c4 = (i & 15) * 4;
            const size_t base = (size_t)(bb * T_ + kbase + row) * C3_ + hh * D_ + c4;
            float4 kv = *(const float4*)&g_qkv[base + C_];
            kv.x = to_tf32(kv.x); kv.y = to_tf32(kv.y);
            kv.z = to_tf32(kv.z); kv.w = to_tf32(kv.w);
            *(float4*)&Ks[row * KS_STRIDE + c4] = kv;
            float4 vv = *(const float4*)&g_qkv[base + 2 * C_];
            vv.x = to_tf32(vv.x); vv.y = to_tf32(vv.y);
            vv.z = to_tf32(vv.z); vv.w = to_tf32(vv.w);
            *(float4*)&Vs[row * VS_STRIDE + c4] = vv;
        }
        if (tid < 32) Ams[tid] = amask[bb * T_ + kbase + tid];
        __syncthreads();

        const bool act = (kbase <= qlo + 15);
        if (act) {
            // --- S = Q K^T (m16 n32 k64) ---
            float s[4][4];
            #pragma unroll
            for (int nb = 0; nb < 4; nb++)
                #pragma unroll
                for (int j = 0; j < 4; j++) s[nb][j] = 0.f;
            #pragma unroll
            for (int kf = 0; kf < 8; kf++) {
                #pragma unroll
                for (int nb = 0; nb < 4; nb++) {
                    uint32_t bf[2];
                    bf[0] = __float_as_uint(Ks[(nb * 8 + r) * KS_STRIDE + kf * 8 + c]);
                    bf[1] = __float_as_uint(Ks[(nb * 8 + r) * KS_STRIDE + kf * 8 + c + 4]);
                    mma_tf32(s[nb], qa[kf], bf);
                }
            }

            // --- scale + padding mask + causal mask ---
            const bool needmask = (kbase + 31 > qlo);
            #pragma unroll
            for (int nb = 0; nb < 4; nb++) {
                const float a0 = Ams[nb * 8 + 2 * c];
                const float a1 = Ams[nb * 8 + 2 * c + 1];
                s[nb][0] = s[nb][0] * 0.125f + a0;
                s[nb][1] = s[nb][1] * 0.125f + a1;
                s[nb][2] = s[nb][2] * 0.125f + a0;
                s[nb][3] = s[nb][3] * 0.125f + a1;
                if (needmask) {
                    const int kc0 = kbase + nb * 8 + 2 * c;
                    const int q0 = qlo + r;
                    if (kc0 > q0)         s[nb][0] = -INFINITY;
                    if (kc0 + 1 > q0)     s[nb][1] = -INFINITY;
                    if (kc0 > q0 + 8)     s[nb][2] = -INFINITY;
                    if (kc0 + 1 > q0 + 8) s[nb][3] = -INFINITY;
                }
            }

            __syncwarp();   // prev tile's P reads done before overwrite

            // --- online softmax (two row-halves per lane) ---
            #pragma unroll
            for (int hf = 0; hf < 2; hf++) {
                float mx = -INFINITY;
                #pragma unroll
                for (int nb = 0; nb < 4; nb++)
                    mx = fmaxf(mx, fmaxf(s[nb][2 * hf], s[nb][2 * hf + 1]));
                mx = fmaxf(mx, __shfl_xor_sync(0xffffffffu, mx, 1));
                mx = fmaxf(mx, __shfl_xor_sync(0xffffffffu, mx, 2));
                const float mnew = fmaxf(mrow[hf], mx);
                const float corr = __expf(mrow[hf] - mnew);
                float sum = 0.f;
                const int prow = w * 16 + r + 8 * hf;
                #pragma unroll
                for (int nb = 0; nb < 4; nb++) {
                    const float p0 = __expf(s[nb][2 * hf] - mnew);
                    const float p1 = __expf(s[nb][2 * hf + 1] - mnew);
                    sum += p0 + p1;
                    Ps[prow * PS_STRIDE + nb * 8 + 2 * c]     = to_tf32(p0);
                    Ps[prow * PS_STRIDE + nb * 8 + 2 * c + 1] = to_tf32(p1);
                }
                sum += __shfl_xor_sync(0xffffffffu, sum, 1);
                sum += __shfl_xor_sync(0xffffffffu, sum, 2);
                lrow[hf] = lrow[hf] * corr + sum;
                mrow[hf] = mnew;
                #pragma unroll
                for (int nb = 0; nb < 8; nb++) {
                    o[nb][2 * hf]     *= corr;
                    o[nb][2 * hf + 1] *= corr;
                }
            }
            __syncwarp();   // P visible to whole warp

            // --- O += P V (m16 n64 k32) ---
            #pragma unroll
            for (int kf = 0; kf < 4; kf++) {
                uint32_t pa[4];
                const int prow = w * 16 + r;
                pa[0] = __float_as_uint(Ps[prow * PS_STRIDE + kf * 8 + c]);
                pa[1] = __float_as_uint(Ps[(prow + 8) * PS_STRIDE + kf * 8 + c]);
                pa[2] = __float_as_uint(Ps[prow * PS_STRIDE + kf * 8 + c + 4]);
                pa[3] = __float_as_uint(Ps[(prow + 8) * PS_STRIDE + kf * 8 + c + 4]);
                #pragma unroll
                for (int nb = 0; nb < 8; nb++) {
                    uint32_t bf[2];
                    bf[0] = __float_as_uint(Vs[(kf * 8 + c) * VS_STRIDE + nb * 8 + r]);
                    bf[1] = __float_as_uint(Vs[(kf * 8 + c + 4) * VS_STRIDE + nb * 8 + r]);
                    mma_tf32(o[nb], pa, bf);
                }
            }
        }
    }

    // --- epilogue: O / l -> g_y ---
    const float inv0 = 1.f / lrow[0];
    const float inv1 = 1.f / lrow[1];
    const int row0 = bb * T_ + qbase + w * 16 + r;
    #pragma unroll
    for (int nb = 0; nb < 8; nb++) {
        const int col = hh * D_ + nb * 8 + 2 * c;
        float2 v0 = { o[nb][0] * inv0, o[nb][1] * inv0 };
        float2 v1 = { o[nb][2] * inv1, o[nb][3] * inv1 };
        *(float2*)&g_y[(size_t)row0 * C_ + col] = v0;
        *(float2*)&g_y[(size_t)(row0 + 8) * C_ + col] = v1;
    }
}

// ----------------------------------------------------------------------------
// Launch.  Inputs: 0 x, 1 attention_mask, 2 attention_bias, 3 W_attn,
//                  4 b_attn, 5 W_proj, 6 b_proj
// ----------------------------------------------------------------------------
extern "C" void kernel_launch(void* const* d_in, const int* in_sizes, int n_in,
                              void* d_out, int out_size)
{
    (void)in_sizes; (void)n_in; (void)out_size;
    const float* x      = (const float*)d_in[0];
    const float* amask  = (const float*)d_in[1];
    const float* W_attn = (const float*)d_in[3];
    const float* b_attn = (const float*)d_in[4];
    const float* W_proj = (const float*)d_in[5];
    const float* b_proj = (const float*)d_in[6];
    float* out = (float*)d_out;

    float *qkv_ptr = nullptr, *y_ptr = nullptr, *wt1 = nullptr, *wt2 = nullptr;
    cudaGetSymbolAddress((void**)&qkv_ptr, g_qkv);
    cudaGetSymbolAddress((void**)&y_ptr, g_y);
    cudaGetSymbolAddress((void**)&wt1, g_WT1);
    cudaGetSymbolAddress((void**)&wt2, g_WT2);

    // 0) Pre-transpose + tf32-round the weights
    transpose_tf32_kernel<<<dim3(C3_ / 32, C_ / 32), dim3(32, 8)>>>(W_attn, wt1, C_, C3_);
    transpose_tf32_kernel<<<dim3(C_ / 32, C_ / 32), dim3(32, 8)>>>(W_proj, wt2, C_, C_);

    // 1) QKV projection
    gemm_mma_kernel<<<dim3(C3_ / 128, BT_ / 128), 256>>>(x, wt1, b_attn, qkv_ptr, BT_, C3_, C_);

    // 2) Causal flash attention (tensor cores)
    attn_mma_kernel<<<dim3(T_ / 64, H_, B_), 128>>>(amask);

    // 3) Output projection
    gemm_mma_kernel<<<dim3(C_ / 128, BT_ / 128), 256>>>(y_ptr, wt2, b_proj, out, BT_, C_, C_);
}

// round 5
// speedup vs baseline: 3.2193x; 1.1001x over previous
#include <cuda_runtime.h>
#include <cstdint>
#include <math.h>

// Problem constants
#define B_  2
#define T_  2048
#define C_  1024
#define H_  16
#define D_  64
#define BT_ (B_*T_)          // 4096
#define C3_ (3*C_)           // 3072

// Scratch (device globals: allocation-guard safe)
__device__ float g_qkv[BT_ * C3_];   // (B*T, 3C)
__device__ float g_y[BT_ * C_];      // (B*T, C) attention output
__device__ float g_WT1[C3_ * C_];    // W_attn^T  (3072 x 1024), tf32-rounded
__device__ float g_WT2[C_ * C_];     // W_proj^T  (1024 x 1024), tf32-rounded

__device__ __forceinline__ float to_tf32(float f) {
    uint32_t u;
    asm("cvt.rna.tf32.f32 %0, %1;" : "=r"(u) : "f"(f));
    return __uint_as_float(u);
}
__device__ __forceinline__ uint32_t tf32_bits(float f) {
    uint32_t u;
    asm("cvt.rna.tf32.f32 %0, %1;" : "=r"(u) : "f"(f));
    return u;
}

__device__ __forceinline__ void mma_tf32(float* d, const uint32_t* a, const uint32_t* b) {
    asm volatile(
        "mma.sync.aligned.m16n8k8.row.col.f32.tf32.tf32.f32 "
        "{%0,%1,%2,%3}, {%4,%5,%6,%7}, {%8,%9}, {%0,%1,%2,%3};"
        : "+f"(d[0]), "+f"(d[1]), "+f"(d[2]), "+f"(d[3])
        : "r"(a[0]), "r"(a[1]), "r"(a[2]), "r"(a[3]), "r"(b[0]), "r"(b[1]));
}

__device__ __forceinline__ uint32_t smem_u32(const void* p) {
    uint32_t a;
    asm("{ .reg .u64 t; cvta.to.shared.u64 t, %1; cvt.u32.u64 %0, t; }" : "=r"(a) : "l"(p));
    return a;
}
__device__ __forceinline__ void cp_async16(uint32_t saddr, const void* g) {
    asm volatile("cp.async.cg.shared.global [%0], [%1], 16;" :: "r"(saddr), "l"(g));
}
#define CP_COMMIT()  asm volatile("cp.async.commit_group;" ::: "memory")
#define CP_WAIT(n)   asm volatile("cp.async.wait_group %0;" :: "n"(n) : "memory")

// ============================================================================
// Transpose + tf32-round: out[n][k] = tf32(in[k][n]).
// ============================================================================
__global__ void transpose_tf32_kernel(const float* __restrict__ in, float* __restrict__ out,
                                      int R, int Cc)
{
    __shared__ float tile[32][33];
    const int bx = blockIdx.x * 32;
    const int by = blockIdx.y * 32;
    #pragma unroll
    for (int j = 0; j < 32; j += 8)
        tile[threadIdx.y + j][threadIdx.x] = in[(size_t)(by + threadIdx.y + j) * Cc + bx + threadIdx.x];
    __syncthreads();
    #pragma unroll
    for (int j = 0; j < 32; j += 8)
        out[(size_t)(bx + threadIdx.y + j) * R + by + threadIdx.x] =
            to_tf32(tile[threadIdx.x][threadIdx.y + j]);
}

// ============================================================================
// tf32 mma.sync GEMM:  Cmat[M,N] = A[M,K] @ BT[N,K]^T + bias[N]
// ============================================================================
__global__ __launch_bounds__(256, 2) void gemm_mma_kernel(
    const float* __restrict__ A, const float* __restrict__ BT,
    const float* __restrict__ bias, float* __restrict__ Cmat,
    int M, int N, int K)
{
    __shared__ float As[2][4][128][4];
    __shared__ float Bs[2][4][128][4];

    const int tid  = threadIdx.x;
    const int lane = tid & 31;
    const int warp = tid >> 5;
    const int wr = warp >> 2;
    const int wc = warp & 3;
    const int g  = lane >> 2;
    const int kc = lane & 3;

    const int m0 = blockIdx.y * 128;
    const int n0 = blockIdx.x * 128;

    const int lm  = tid >> 2;
    const int lkq = tid & 3;

    float acc[4][4][4];
    #pragma unroll
    for (int mf = 0; mf < 4; mf++)
        #pragma unroll
        for (int nf = 0; nf < 4; nf++)
            #pragma unroll
            for (int r = 0; r < 4; r++) acc[mf][nf][r] = 0.f;

    const int nch = K >> 4;

    {
        #pragma unroll
        for (int it = 0; it < 2; it++) {
            const int m = lm + it * 64;
            float4 va = *(const float4*)&A[(size_t)(m0 + m) * K + 4 * lkq];
            va.x = to_tf32(va.x); va.y = to_tf32(va.y);
            va.z = to_tf32(va.z); va.w = to_tf32(va.w);
            *(float4*)&As[0][lkq][m][0] = va;
            float4 vb = *(const float4*)&BT[(size_t)(n0 + m) * K + 4 * lkq];
            *(float4*)&Bs[0][lkq][m][0] = vb;
        }
    }
    __syncthreads();

    for (int icn = 0; icn < nch; icn++) {
        const int cur = icn & 1;

        float4 pa[2], pb[2];
        const bool more = (icn + 1) < nch;
        if (more) {
            const int k0 = (icn + 1) << 4;
            #pragma unroll
            for (int it = 0; it < 2; it++) {
                const int m = lm + it * 64;
                pa[it] = *(const float4*)&A[(size_t)(m0 + m) * K + k0 + 4 * lkq];
                pb[it] = *(const float4*)&BT[(size_t)(n0 + m) * K + k0 + 4 * lkq];
            }
        }

        #pragma unroll
        for (int t = 0; t < 2; t++) {
            uint32_t bf[4][2];
            #pragma unroll
            for (int nf = 0; nf < 4; nf++) {
                const int n = wc * 32 + nf * 8 + g;
                bf[nf][0] = __float_as_uint(Bs[cur][2 * t + 0][n][kc]);
                bf[nf][1] = __float_as_uint(Bs[cur][2 * t + 1][n][kc]);
            }
            #pragma unroll
            for (int mf = 0; mf < 4; mf++) {
                const int m = wr * 64 + mf * 16 + g;
                uint32_t af[4];
                af[0] = __float_as_uint(As[cur][2 * t + 0][m][kc]);
                af[1] = __float_as_uint(As[cur][2 * t + 0][m + 8][kc]);
                af[2] = __float_as_uint(As[cur][2 * t + 1][m][kc]);
                af[3] = __float_as_uint(As[cur][2 * t + 1][m + 8][kc]);
                #pragma unroll
                for (int nf = 0; nf < 4; nf++)
                    mma_tf32(acc[mf][nf], af, bf[nf]);
            }
        }

        if (more) {
            const int nxt = cur ^ 1;
            #pragma unroll
            for (int it = 0; it < 2; it++) {
                const int m = lm + it * 64;
                float4 va = pa[it];
                va.x = to_tf32(va.x); va.y = to_tf32(va.y);
                va.z = to_tf32(va.z); va.w = to_tf32(va.w);
                *(float4*)&As[nxt][lkq][m][0] = va;
                *(float4*)&Bs[nxt][lkq][m][0] = pb[it];
            }
            __syncthreads();
        }
    }

    #pragma unroll
    for (int mf = 0; mf < 4; mf++) {
        const int row = m0 + wr * 64 + mf * 16 + g;
        #pragma unroll
        for (int nf = 0; nf < 4; nf++) {
            const int col = n0 + wc * 32 + nf * 8 + kc * 2;
            const float b0 = bias[col];
            const float b1 = bias[col + 1];
            float2 o0 = { acc[mf][nf][0] + b0, acc[mf][nf][1] + b1 };
            float2 o1 = { acc[mf][nf][2] + b0, acc[mf][nf][3] + b1 };
            *(float2*)&Cmat[(size_t)row * N + col] = o0;
            *(float2*)&Cmat[(size_t)(row + 8) * N + col] = o1;
        }
    }
}

// ============================================================================
// Flash attention (causal), tf32 mma.sync, cp.async double-buffered K/V.
// Grid (T/64, H, B), heavy-first qt order. Block 128 (4 warps).
// Q tile 64 (16 rows/warp), K tile 32.
// ============================================================================
#define KS_STRIDE 68
#define VS_STRIDE 72
#define PS_STRIDE 36

__global__ __launch_bounds__(128) void attn_mma_kernel(const float* __restrict__ amask)
{
    __shared__ __align__(16) float Ks[2][32 * KS_STRIDE];   // also Q staging (4352 floats x2)
    __shared__ __align__(16) float Vs[2][32 * VS_STRIDE];
    __shared__ __align__(16) float Ps[64 * PS_STRIDE];
    __shared__ float Ams[2][32];

    const int qt = (gridDim.x - 1) - blockIdx.x;   // heavy CTAs first
    const int hh = blockIdx.y;
    const int bb = blockIdx.z;
    const int tid = threadIdx.x;
    const int lane = tid & 31;
    const int w = tid >> 5;
    const int r = lane >> 2;
    const int c = lane & 3;
    const int qbase = qt * 64;
    const int qlo = qbase + w * 16;

    const uint32_t ksb = smem_u32(&Ks[0][0]);
    const uint32_t vsb = smem_u32(&Vs[0][0]);

    // --- stage Q (tf32-rounded) into the Ks region, cache fragments ---
    float* Qstage = &Ks[0][0];   // 64 rows, stride KS_STRIDE
    for (int i = tid; i < 64 * 16; i += 128) {
        const int row = i >> 4;
        const int c4 = (i & 15) * 4;
        float4 v = *(const float4*)&g_qkv[(size_t)(bb * T_ + qbase + row) * C3_ + hh * D_ + c4];
        v.x = to_tf32(v.x); v.y = to_tf32(v.y);
        v.z = to_tf32(v.z); v.w = to_tf32(v.w);
        *(float4*)&Qstage[row * KS_STRIDE + c4] = v;
    }
    __syncthreads();

    uint32_t qa[8][4];
    #pragma unroll
    for (int kf = 0; kf < 8; kf++) {
        const int row = w * 16 + r;
        const int col = kf * 8 + c;
        qa[kf][0] = __float_as_uint(Qstage[row * KS_STRIDE + col]);
        qa[kf][1] = __float_as_uint(Qstage[(row + 8) * KS_STRIDE + col]);
        qa[kf][2] = __float_as_uint(Qstage[row * KS_STRIDE + col + 4]);
        qa[kf][3] = __float_as_uint(Qstage[(row + 8) * KS_STRIDE + col + 4]);
    }
    __syncthreads();   // Q reads done before cp.async overwrites Ks

    const int nkt = 2 * qt + 2;

    // --- prologue: tile 0 -> buf 0 ---
    {
        const size_t rb = (size_t)(bb * T_) * C3_ + hh * D_;
        for (int idx = tid; idx < 512; idx += 128) {
            const int row = idx >> 4;
            const int c4 = (idx & 15) * 4;
            const float* gk = &g_qkv[rb + (size_t)row * C3_ + C_ + c4];
            cp_async16(ksb + (uint32_t)(row * KS_STRIDE + c4) * 4u, gk);
            cp_async16(vsb + (uint32_t)(row * VS_STRIDE + c4) * 4u, gk + C_);
        }
        if (tid < 32) Ams[0][tid] = amask[bb * T_ + tid];
        CP_COMMIT();
    }

    float o[8][4];
    #pragma unroll
    for (int nb = 0; nb < 8; nb++)
        #pragma unroll
        for (int j = 0; j < 4; j++) o[nb][j] = 0.f;
    float mrow[2] = { -INFINITY, -INFINITY };
    float lrow[2] = { 0.f, 0.f };

    for (int kt = 0; kt < nkt; kt++) {
        const int buf = kt & 1;
        const int kbase = kt * 32;
        const bool more = (kt + 1) < nkt;

        if (more) {
            const int nb2 = buf ^ 1;
            const size_t rb = (size_t)(bb * T_ + kbase + 32) * C3_ + hh * D_;
            const uint32_t kdst = ksb + (uint32_t)(nb2 * 32 * KS_STRIDE) * 4u;
            const uint32_t vdst = vsb + (uint32_t)(nb2 * 32 * VS_STRIDE) * 4u;
            for (int idx = tid; idx < 512; idx += 128) {
                const int row = idx >> 4;
                const int c4 = (idx & 15) * 4;
                const float* gk = &g_qkv[rb + (size_t)row * C3_ + C_ + c4];
                cp_async16(kdst + (uint32_t)(row * KS_STRIDE + c4) * 4u, gk);
                cp_async16(vdst + (uint32_t)(row * VS_STRIDE + c4) * 4u, gk + C_);
            }
            if (tid < 32) Ams[nb2][tid] = amask[bb * T_ + kbase + 32 + tid];
            CP_COMMIT();
            CP_WAIT(1);   // tile kt arrived
        } else {
            CP_WAIT(0);
        }
        __syncthreads();

        const bool act = (kbase <= qlo + 15);
        if (act) {
            const float* ksB = &Ks[buf][0];
            const float* vsB = &Vs[buf][0];

            // --- S = Q K^T ---
            float s[4][4];
            #pragma unroll
            for (int nb = 0; nb < 4; nb++)
                #pragma unroll
                for (int j = 0; j < 4; j++) s[nb][j] = 0.f;
            #pragma unroll
            for (int kf = 0; kf < 8; kf++) {
                #pragma unroll
                for (int nb = 0; nb < 4; nb++) {
                    uint32_t bf[2];
                    bf[0] = tf32_bits(ksB[(nb * 8 + r) * KS_STRIDE + kf * 8 + c]);
                    bf[1] = tf32_bits(ksB[(nb * 8 + r) * KS_STRIDE + kf * 8 + c + 4]);
                    mma_tf32(s[nb], qa[kf], bf);
                }
            }

            // --- scale + masks ---
            const bool needmask = (kbase + 31 > qlo);
            #pragma unroll
            for (int nb = 0; nb < 4; nb++) {
                const float a0 = Ams[buf][nb * 8 + 2 * c];
                const float a1 = Ams[buf][nb * 8 + 2 * c + 1];
                s[nb][0] = s[nb][0] * 0.125f + a0;
                s[nb][1] = s[nb][1] * 0.125f + a1;
                s[nb][2] = s[nb][2] * 0.125f + a0;
                s[nb][3] = s[nb][3] * 0.125f + a1;
                if (needmask) {
                    const int kc0 = kbase + nb * 8 + 2 * c;
                    const int q0 = qlo + r;
                    if (kc0 > q0)         s[nb][0] = -INFINITY;
                    if (kc0 + 1 > q0)     s[nb][1] = -INFINITY;
                    if (kc0 > q0 + 8)     s[nb][2] = -INFINITY;
                    if (kc0 + 1 > q0 + 8) s[nb][3] = -INFINITY;
                }
            }

            __syncwarp();   // prev tile's P reads done before overwrite

            // --- online softmax ---
            #pragma unroll
            for (int hf = 0; hf < 2; hf++) {
                float mx = -INFINITY;
                #pragma unroll
                for (int nb = 0; nb < 4; nb++)
                    mx = fmaxf(mx, fmaxf(s[nb][2 * hf], s[nb][2 * hf + 1]));
                mx = fmaxf(mx, __shfl_xor_sync(0xffffffffu, mx, 1));
                mx = fmaxf(mx, __shfl_xor_sync(0xffffffffu, mx, 2));
                const float mnew = fmaxf(mrow[hf], mx);
                const float corr = __expf(mrow[hf] - mnew);
                float sum = 0.f;
                const int prow = w * 16 + r + 8 * hf;
                #pragma unroll
                for (int nb = 0; nb < 4; nb++) {
                    const float p0 = __expf(s[nb][2 * hf] - mnew);
                    const float p1 = __expf(s[nb][2 * hf + 1] - mnew);
                    sum += p0 + p1;
                    Ps[prow * PS_STRIDE + nb * 8 + 2 * c]     = to_tf32(p0);
                    Ps[prow * PS_STRIDE + nb * 8 + 2 * c + 1] = to_tf32(p1);
                }
                sum += __shfl_xor_sync(0xffffffffu, sum, 1);
                sum += __shfl_xor_sync(0xffffffffu, sum, 2);
                lrow[hf] = lrow[hf] * corr + sum;
                mrow[hf] = mnew;
                #pragma unroll
                for (int nb = 0; nb < 8; nb++) {
                    o[nb][2 * hf]     *= corr;
                    o[nb][2 * hf + 1] *= corr;
                }
            }
            __syncwarp();

            // --- O += P V ---
            #pragma unroll
            for (int kf = 0; kf < 4; kf++) {
                uint32_t pa[4];
                const int prow = w * 16 + r;
                pa[0] = __float_as_uint(Ps[prow * PS_STRIDE + kf * 8 + c]);
                pa[1] = __float_as_uint(Ps[(prow + 8) * PS_STRIDE + kf * 8 + c]);
                pa[2] = __float_as_uint(Ps[prow * PS_STRIDE + kf * 8 + c + 4]);
                pa[3] = __float_as_uint(Ps[(prow + 8) * PS_STRIDE + kf * 8 + c + 4]);
                #pragma unroll
                for (int nb = 0; nb < 8; nb++) {
                    uint32_t bf[2];
                    bf[0] = tf32_bits(vsB[(kf * 8 + c) * VS_STRIDE + nb * 8 + r]);
                    bf[1] = tf32_bits(vsB[(kf * 8 + c + 4) * VS_STRIDE + nb * 8 + r]);
                    mma_tf32(o[nb], pa, bf);
                }
            }
        }
        __syncthreads();   // all reads of buf done before cp.async reuses it
    }

    // --- epilogue ---
    const float inv0 = 1.f / lrow[0];
    const float inv1 = 1.f / lrow[1];
    const int row0 = bb * T_ + qbase + w * 16 + r;
    #pragma unroll
    for (int nb = 0; nb < 8; nb++) {
        const int col = hh * D_ + nb * 8 + 2 * c;
        float2 v0 = { o[nb][0] * inv0, o[nb][1] * inv0 };
        float2 v1 = { o[nb][2] * inv1, o[nb][3] * inv1 };
        *(float2*)&g_y[(size_t)row0 * C_ + col] = v0;
        *(float2*)&g_y[(size_t)(row0 + 8) * C_ + col] = v1;
    }
}

// ----------------------------------------------------------------------------
// Launch.  Inputs: 0 x, 1 attention_mask, 2 attention_bias, 3 W_attn,
//                  4 b_attn, 5 W_proj, 6 b_proj
// ----------------------------------------------------------------------------
extern "C" void kernel_launch(void* const* d_in, const int* in_sizes, int n_in,
                              void* d_out, int out_size)
{
    (void)in_sizes; (void)n_in; (void)out_size;
    const float* x      = (const float*)d_in[0];
    const float* amask  = (const float*)d_in[1];
    const float* W_attn = (const float*)d_in[3];
    const float* b_attn = (const float*)d_in[4];
    const float* W_proj = (const float*)d_in[5];
    const float* b_proj = (const float*)d_in[6];
    float* out = (float*)d_out;

    float *qkv_ptr = nullptr, *y_ptr = nullptr, *wt1 = nullptr, *wt2 = nullptr;
    cudaGetSymbolAddress((void**)&qkv_ptr, g_qkv);
    cudaGetSymbolAddress((void**)&y_ptr, g_y);
    cudaGetSymbolAddress((void**)&wt1, g_WT1);
    cudaGetSymbolAddress((void**)&wt2, g_WT2);

    // 0) Pre-transpose + tf32-round the weights
    transpose_tf32_kernel<<<dim3(C3_ / 32, C_ / 32), dim3(32, 8)>>>(W_attn, wt1, C_, C3_);
    transpose_tf32_kernel<<<dim3(C_ / 32, C_ / 32), dim3(32, 8)>>>(W_proj, wt2, C_, C_);

    // 1) QKV projection
    gemm_mma_kernel<<<dim3(C3_ / 128, BT_ / 128), 256>>>(x, wt1, b_attn, qkv_ptr, BT_, C3_, C_);

    // 2) Causal flash attention (tensor cores, pipelined)
    attn_mma_kernel<<<dim3(T_ / 64, H_, B_), 128>>>(amask);

    // 3) Output projection
    gemm_mma_kernel<<<dim3(C_ / 128, BT_ / 128), 256>>>(y_ptr, wt2, b_proj, out, BT_, C_, C_);
}